// round 2
// baseline (speedup 1.0000x reference)
#include <cuda_runtime.h>
#include <cuda_bf16.h>
#include <cstdint>

#define D_FEAT 64
#define H_FEAT 128
#define N_MAX 100000

// Scratch accumulator: flow_total [N, 64]
__device__ float g_flow[(size_t)N_MAX * D_FEAT];
// 1 if edge_index is int64, 0 if int32 (detected on device)
__device__ int g_is64;

// ---------------------------------------------------------------------------
// Kernel 1: zero accumulator + detect edge_index dtype
// ---------------------------------------------------------------------------
__global__ void zero_kernel(int n_float4, const int* __restrict__ edge_index_raw) {
    int i = blockIdx.x * blockDim.x + threadIdx.x;
    if (i < n_float4) {
        ((float4*)g_flow)[i] = make_float4(0.f, 0.f, 0.f, 0.f);
    }
    if (blockIdx.x == 0 && threadIdx.x == 0) {
        // int64 values are < 2^31 and nonnegative -> every odd 32-bit word is 0.
        // int32 values at odd positions are random node ids (nonzero w.h.p.).
        int all_zero = 1;
#pragma unroll
        for (int k = 0; k < 8; k++) {
            if (edge_index_raw[2 * k + 1] != 0) all_zero = 0;
        }
        g_is64 = all_zero;
    }
}

// ---------------------------------------------------------------------------
// Kernel 2: scatter-add edge_attr into both endpoints.
// One thread per (edge, 16-byte chunk). red.add.v4.f32: no return value,
// 4 floats per atomic op. Accumulator (25.6 MB) is L2-resident.
// ---------------------------------------------------------------------------
__device__ __forceinline__ void red_add_v4(float* addr, float4 v) {
    size_t gaddr = __cvta_generic_to_global(addr);
    asm volatile("red.global.add.v4.f32 [%0], {%1, %2, %3, %4};"
                 :: "l"(gaddr), "f"(v.x), "f"(v.y), "f"(v.z), "f"(v.w)
                 : "memory");
}

__global__ void scatter_kernel(const void* __restrict__ edge_index,
                               const float* __restrict__ edge_attr,
                               int E, int N) {
    long long t = (long long)blockIdx.x * blockDim.x + threadIdx.x;
    int e = (int)(t >> 4);
    int c = (int)(t & 15);
    if (e >= E) return;

    long long past, future;
    if (g_is64) {
        const long long* ei = (const long long*)edge_index;
        past   = __ldg(&ei[e]);
        future = __ldg(&ei[(size_t)E + e]);
    } else {
        const int* ei = (const int*)edge_index;
        past   = __ldg(&ei[e]);
        future = __ldg(&ei[(size_t)E + e]);
    }

    float4 v = ((const float4*)edge_attr)[(size_t)e * 16 + c];

    if ((unsigned long long)future < (unsigned long long)N)
        red_add_v4(g_flow + (size_t)future * D_FEAT + c * 4, v);
    if ((unsigned long long)past < (unsigned long long)N)
        red_add_v4(g_flow + (size_t)past * D_FEAT + c * 4, v);
}

// ---------------------------------------------------------------------------
// Kernel 3: fused MLP  out = relu(flow @ W1 + b1) @ W2 + b2
// W1/W2 in 64 KB dynamic shared (broadcast LDS.128). One node row per thread,
// float4 blocking -> 4 independent FMA chains.
// ---------------------------------------------------------------------------
__global__ void __launch_bounds__(256) mlp_kernel(
    const float* __restrict__ W1, const float* __restrict__ b1,
    const float* __restrict__ W2, const float* __restrict__ b2,
    float* __restrict__ out, int N) {

    extern __shared__ float smem[];
    float* sW1 = smem;                    // [k][j] row-major, 64x128
    float* sW2 = smem + D_FEAT * H_FEAT;  // [j][m] row-major, 128x64

    for (int i = threadIdx.x; i < (D_FEAT * H_FEAT) / 4; i += blockDim.x) {
        ((float4*)sW1)[i] = ((const float4*)W1)[i];
        ((float4*)sW2)[i] = ((const float4*)W2)[i];
    }
    __syncthreads();

    int row = blockIdx.x * blockDim.x + threadIdx.x;
    if (row >= N) return;

    float x[D_FEAT];
    const float4* xr = (const float4*)(g_flow + (size_t)row * D_FEAT);
#pragma unroll
    for (int i = 0; i < D_FEAT / 4; i++) {
        float4 v = xr[i];
        x[4 * i + 0] = v.x; x[4 * i + 1] = v.y;
        x[4 * i + 2] = v.z; x[4 * i + 3] = v.w;
    }

    float acc_out[D_FEAT];
#pragma unroll
    for (int i = 0; i < D_FEAT / 4; i++) {
        float4 bv = __ldg(&((const float4*)b2)[i]);
        acc_out[4 * i + 0] = bv.x; acc_out[4 * i + 1] = bv.y;
        acc_out[4 * i + 2] = bv.z; acc_out[4 * i + 3] = bv.w;
    }

    for (int j = 0; j < H_FEAT; j += 4) {
        float4 acc = __ldg(&((const float4*)b1)[j / 4]);
#pragma unroll
        for (int k = 0; k < D_FEAT; k++) {
            float4 w = *(const float4*)(sW1 + k * H_FEAT + j);
            acc.x += x[k] * w.x;
            acc.y += x[k] * w.y;
            acc.z += x[k] * w.z;
            acc.w += x[k] * w.w;
        }
        acc.x = fmaxf(acc.x, 0.f);
        acc.y = fmaxf(acc.y, 0.f);
        acc.z = fmaxf(acc.z, 0.f);
        acc.w = fmaxf(acc.w, 0.f);

#pragma unroll
        for (int m = 0; m < D_FEAT; m += 4) {
            float4 w0 = *(const float4*)(sW2 + (j + 0) * D_FEAT + m);
            float4 w1 = *(const float4*)(sW2 + (j + 1) * D_FEAT + m);
            float4 w2 = *(const float4*)(sW2 + (j + 2) * D_FEAT + m);
            float4 w3 = *(const float4*)(sW2 + (j + 3) * D_FEAT + m);
            acc_out[m + 0] += acc.x * w0.x + acc.y * w1.x + acc.z * w2.x + acc.w * w3.x;
            acc_out[m + 1] += acc.x * w0.y + acc.y * w1.y + acc.z * w2.y + acc.w * w3.y;
            acc_out[m + 2] += acc.x * w0.z + acc.y * w1.z + acc.z * w2.z + acc.w * w3.z;
            acc_out[m + 3] += acc.x * w0.w + acc.y * w1.w + acc.z * w2.w + acc.w * w3.w;
        }
    }

    float4* orow = (float4*)(out + (size_t)row * D_FEAT);
#pragma unroll
    for (int i = 0; i < D_FEAT / 4; i++) {
        orow[i] = make_float4(acc_out[4 * i + 0], acc_out[4 * i + 1],
                              acc_out[4 * i + 2], acc_out[4 * i + 3]);
    }
}

// ---------------------------------------------------------------------------
// kernel_launch
// ---------------------------------------------------------------------------
extern "C" void kernel_launch(void* const* d_in, const int* in_sizes, int n_in,
                              void* d_out, int out_size) {
    int idx = 0;
    const void* edge_index = d_in[idx];
    idx++;
    const float* edge_attr = (const float*)d_in[idx];
    int E = in_sizes[idx] / D_FEAT;   // derive E from edge_attr [E,64]
    idx++;
    // skip scalar num_nodes if present
    while (idx < n_in && in_sizes[idx] <= 1) idx++;
    const float* W1 = (const float*)d_in[idx++];
    const float* b1 = (const float*)d_in[idx++];
    const float* W2 = (const float*)d_in[idx++];
    const float* b2 = (const float*)d_in[idx++];
    float* out = (float*)d_out;

    int N = out_size / D_FEAT;  // 100000

    // 1) zero accumulator + detect index dtype
    {
        int n_f4 = (N * D_FEAT) / 4;
        int blocks = (n_f4 + 255) / 256;
        zero_kernel<<<blocks, 256>>>(n_f4, (const int*)edge_index);
    }

    // 2) scatter-add
    {
        long long threads = (long long)E * 16;
        int blocks = (int)((threads + 255) / 256);
        scatter_kernel<<<blocks, 256>>>(edge_index, edge_attr, E, N);
    }

    // 3) fused MLP
    {
        int blocks = (N + 255) / 256;
        size_t shmem = 2 * (size_t)D_FEAT * H_FEAT * sizeof(float);  // 64 KB
        cudaFuncSetAttribute(mlp_kernel,
                             cudaFuncAttributeMaxDynamicSharedMemorySize,
                             (int)shmem);
        mlp_kernel<<<blocks, 256, shmem>>>(W1, b1, W2, b2, out, N);
    }
}